// round 1
// baseline (speedup 1.0000x reference)
#include <cuda_runtime.h>

#define S_LEN 2048
#define NH 16
#define HD 64
#define NB 2
#define ATT_SCALE 0.125f

// Scratch (allocation-free rule: __device__ globals)
__device__ float g_q[NB * NH * S_LEN * HD];   // [b][h][s][d]
__device__ float g_k[NB * NH * S_LEN * HD];
__device__ float g_v[NB * NH * S_LEN * HD];
__device__ float g_o[NB * S_LEN * 1024];      // [b][s][h*64+d]

// ---------------------------------------------------------------------------
// SGEMM: C[m,n] = sum_k A[m,k] * Bw[n,k]   (both K-major, K = 1024 fixed)
// Tile 128x128, K-step 8, 256 threads, 8x8 per thread.
// MODE 0: A = x, scatter C into g_q/g_k/g_v per-head layout.
// MODE 1: A = g_o (ignore A arg), plain row-major store to C.
// ---------------------------------------------------------------------------
template <int MODE>
__global__ void __launch_bounds__(256) sgemm_nt(const float* __restrict__ A,
                                                const float* __restrict__ Bw,
                                                float* __restrict__ C)
{
    __shared__ float As[8][128];
    __shared__ float Bs[8][128];

    const int tid = threadIdx.x;
    const int bm = blockIdx.y * 128;
    const int bn = blockIdx.x * 128;

    const float* Ap = (MODE == 1) ? (const float*)g_o : A;

    const int lr = tid >> 1;            // 0..127
    const int lk = (tid & 1) * 4;       // 0 or 4
    const float* aload = Ap + (size_t)(bm + lr) * 1024 + lk;
    const float* bload = Bw + (size_t)(bn + lr) * 1024 + lk;

    const int lane = tid & 31;
    const int warp = tid >> 5;
    const int wr = (warp & 3) * 32 + (lane & 3) * 8;    // row base (0..120)
    const int wc = (warp >> 2) * 64 + (lane >> 2) * 8;  // col base (0..120)

    float acc[8][8];
#pragma unroll
    for (int i = 0; i < 8; i++)
#pragma unroll
        for (int j = 0; j < 8; j++) acc[i][j] = 0.f;

    for (int kt = 0; kt < 1024; kt += 8) {
        float4 av = *(const float4*)(aload + kt);
        float4 bv = *(const float4*)(bload + kt);
        As[lk + 0][lr] = av.x; As[lk + 1][lr] = av.y;
        As[lk + 2][lr] = av.z; As[lk + 3][lr] = av.w;
        Bs[lk + 0][lr] = bv.x; Bs[lk + 1][lr] = bv.y;
        Bs[lk + 2][lr] = bv.z; Bs[lk + 3][lr] = bv.w;
        __syncthreads();
#pragma unroll
        for (int kk = 0; kk < 8; kk++) {
            float a[8], b[8];
            *(float4*)(a)     = *(const float4*)&As[kk][wr];
            *(float4*)(a + 4) = *(const float4*)&As[kk][wr + 4];
            *(float4*)(b)     = *(const float4*)&Bs[kk][wc];
            *(float4*)(b + 4) = *(const float4*)&Bs[kk][wc + 4];
#pragma unroll
            for (int i = 0; i < 8; i++)
#pragma unroll
                for (int j = 0; j < 8; j++)
                    acc[i][j] = fmaf(a[i], b[j], acc[i][j]);
        }
        __syncthreads();
    }

    if (MODE == 0) {
        // scatter into per-head q/k/v layout
#pragma unroll
        for (int i = 0; i < 8; i++) {
            int m = bm + wr + i;
            int b_ = m >> 11;
            int s_ = m & 2047;
#pragma unroll
            for (int j = 0; j < 8; j++) {
                int n = bn + wc + j;          // 0..3071
                int which = n >> 10;          // 0=q 1=k 2=v
                int r = n & 1023;
                int h = r >> 6;
                int d = r & 63;
                float* dst = (which == 0) ? g_q : (which == 1) ? g_k : g_v;
                dst[(((size_t)b_ * NH + h) * S_LEN + s_) * HD + d] = acc[i][j];
            }
        }
    } else {
#pragma unroll
        for (int i = 0; i < 8; i++) {
            size_t row = (size_t)(bm + wr + i) * 1024 + bn + wc;
            *(float4*)&C[row]     = make_float4(acc[i][0], acc[i][1], acc[i][2], acc[i][3]);
            *(float4*)&C[row + 4] = make_float4(acc[i][4], acc[i][5], acc[i][6], acc[i][7]);
        }
    }
}

// ---------------------------------------------------------------------------
// Flash attention, fp32. One block per (b,h, 64-query tile).
// 256 threads as 16x16; each thread owns a 4x4 fragment.
// Smem: Qt[d][row], Kt[d][key] (reused as P[row][key]), Vs[key][d]  = 48 KB.
// ---------------------------------------------------------------------------
__global__ void __launch_bounds__(256) flash_kernel()
{
    __shared__ float Qt[64 * 64];   // transposed: Qt[d*64 + row]
    __shared__ float Kt[64 * 64];   // transposed: Kt[d*64 + key]; reused as P[row*64+key]
    __shared__ float Vs[64 * 64];   // natural:    Vs[key*64 + d]

    const int tid = threadIdx.x;
    const int qt = blockIdx.x;      // 0..31 query tiles
    const int bh = blockIdx.y;      // 0..31 (b*16+h)

    const float* qg = g_q + (size_t)bh * S_LEN * HD;
    const float* kg = g_k + (size_t)bh * S_LEN * HD;
    const float* vg = g_v + (size_t)bh * S_LEN * HD;

    const int ls  = tid >> 2;         // 0..63 row/key for loading
    const int ld0 = (tid & 3) * 16;   // 0,16,32,48

    // Load Q tile transposed (visible after first in-loop __syncthreads)
    {
        const float* src = qg + (size_t)(qt * 64 + ls) * HD + ld0;
#pragma unroll
        for (int it = 0; it < 4; it++) {
            float4 v4 = *(const float4*)(src + it * 4);
            int d = ld0 + it * 4;
            Qt[(d + 0) * 64 + ls] = v4.x;
            Qt[(d + 1) * 64 + ls] = v4.y;
            Qt[(d + 2) * 64 + ls] = v4.z;
            Qt[(d + 3) * 64 + ls] = v4.w;
        }
    }

    const int ty = tid >> 4, tx = tid & 15;
    const int r0 = ty * 4;   // this thread's 4 query rows
    const int c0 = tx * 4;   // this thread's 4 cols (keys in pass 1, dims in pass 2)

    float m_i[4], l_i[4], o[4][4];
#pragma unroll
    for (int i = 0; i < 4; i++) {
        m_i[i] = -1e30f;
        l_i[i] = 0.f;
#pragma unroll
        for (int j = 0; j < 4; j++) o[i][j] = 0.f;
    }

    for (int kt = 0; kt < 32; kt++) {
        // Load K (transposed) and V tiles
        {
            const float* ksrc = kg + (size_t)(kt * 64 + ls) * HD + ld0;
            const float* vsrc = vg + (size_t)(kt * 64 + ls) * HD + ld0;
#pragma unroll
            for (int it = 0; it < 4; it++) {
                int d = ld0 + it * 4;
                float4 v4 = *(const float4*)(ksrc + it * 4);
                Kt[(d + 0) * 64 + ls] = v4.x;
                Kt[(d + 1) * 64 + ls] = v4.y;
                Kt[(d + 2) * 64 + ls] = v4.z;
                Kt[(d + 3) * 64 + ls] = v4.w;
                float4 w4 = *(const float4*)(vsrc + it * 4);
                *(float4*)&Vs[ls * 64 + d] = w4;
            }
        }
        __syncthreads();

        // S = Q @ K^T (64x64x64)
        float s[4][4];
#pragma unroll
        for (int i = 0; i < 4; i++)
#pragma unroll
            for (int j = 0; j < 4; j++) s[i][j] = 0.f;

#pragma unroll 8
        for (int kk = 0; kk < 64; kk++) {
            float4 qf = *(const float4*)&Qt[kk * 64 + r0];
            float4 kf = *(const float4*)&Kt[kk * 64 + c0];
            float qv[4] = {qf.x, qf.y, qf.z, qf.w};
            float kv[4] = {kf.x, kf.y, kf.z, kf.w};
#pragma unroll
            for (int i = 0; i < 4; i++)
#pragma unroll
                for (int j = 0; j < 4; j++)
                    s[i][j] = fmaf(qv[i], kv[j], s[i][j]);
        }

        // Online softmax (row groups share 16 consecutive lanes -> xor shuffles)
#pragma unroll
        for (int i = 0; i < 4; i++) {
            float rm = -1e30f;
#pragma unroll
            for (int j = 0; j < 4; j++) {
                s[i][j] *= ATT_SCALE;
                rm = fmaxf(rm, s[i][j]);
            }
#pragma unroll
            for (int off = 8; off > 0; off >>= 1)
                rm = fmaxf(rm, __shfl_xor_sync(0xffffffffu, rm, off));
            float mnew = fmaxf(m_i[i], rm);
            float scl = __expf(m_i[i] - mnew);
            float rs = 0.f;
#pragma unroll
            for (int j = 0; j < 4; j++) {
                float p = __expf(s[i][j] - mnew);
                s[i][j] = p;
                rs += p;
            }
#pragma unroll
            for (int off = 8; off > 0; off >>= 1)
                rs += __shfl_xor_sync(0xffffffffu, rs, off);
            l_i[i] = l_i[i] * scl + rs;
            m_i[i] = mnew;
#pragma unroll
            for (int j = 0; j < 4; j++) o[i][j] *= scl;
        }

        __syncthreads();   // all reads of Kt done -> safe to reuse as P
#pragma unroll
        for (int i = 0; i < 4; i++)
            *(float4*)&Kt[(r0 + i) * 64 + c0] =
                make_float4(s[i][0], s[i][1], s[i][2], s[i][3]);
        __syncthreads();

        // O += P @ V (64x64x64)
#pragma unroll 8
        for (int kk = 0; kk < 64; kk++) {
            float4 vf = *(const float4*)&Vs[kk * 64 + c0];
            float vv[4] = {vf.x, vf.y, vf.z, vf.w};
#pragma unroll
            for (int i = 0; i < 4; i++) {
                float p = Kt[(r0 + i) * 64 + kk];
#pragma unroll
                for (int j = 0; j < 4; j++)
                    o[i][j] = fmaf(p, vv[j], o[i][j]);
            }
        }
        __syncthreads();   // before next tile overwrites Kt/Vs
    }

    // Normalize and write to g_o in [b][s][h*64+d] layout
    const int b_ = bh >> 4;
    const int h  = bh & 15;
#pragma unroll
    for (int i = 0; i < 4; i++) {
        float inv = 1.f / l_i[i];
        size_t idx = ((size_t)b_ * S_LEN + (size_t)qt * 64 + r0 + i) * 1024 + h * HD + c0;
        *(float4*)&g_o[idx] =
            make_float4(o[i][0] * inv, o[i][1] * inv, o[i][2] * inv, o[i][3] * inv);
    }
}

// ---------------------------------------------------------------------------
extern "C" void kernel_launch(void* const* d_in, const int* in_sizes, int n_in,
                              void* d_out, int out_size)
{
    const float* x     = (const float*)d_in[0];   // [2,2048,1024]
    const float* qkv_w = (const float*)d_in[1];   // [3072,1024]
    const float* out_w = (const float*)d_in[2];   // [1024,1024]
    float* out = (float*)d_out;                   // [2,2048,1024]

    // 1) QKV projection -> per-head q/k/v scratch
    sgemm_nt<0><<<dim3(24, 32), 256>>>(x, qkv_w, nullptr);
    // 2) flash attention -> g_o
    flash_kernel<<<dim3(32, 32), 256>>>();
    // 3) output projection -> d_out
    sgemm_nt<1><<<dim3(8, 32), 256>>>(nullptr, out_w, out);
}

// round 2
// speedup vs baseline: 3.2739x; 3.2739x over previous
#include <cuda_runtime.h>
#include <cstdint>

#define S_LEN 2048
#define NH 16
#define HD 64
#define NB 2
#define ATT_SCALE 0.125f

// Scratch (allocation-free rule: __device__ globals)
__device__ float g_q[NB * NH * S_LEN * HD];   // [b][h][s][d]
__device__ float g_k[NB * NH * S_LEN * HD];
__device__ float g_v[NB * NH * S_LEN * HD];
__device__ float g_o[NB * S_LEN * 1024];      // [b][s][h*64+d]

__device__ __forceinline__ uint32_t f2tf32(float f) {
    uint32_t r;
    asm("cvt.rna.tf32.f32 %0, %1;" : "=r"(r) : "f"(f));
    return r;
}

__device__ __forceinline__ void mma_tf32(float c[4], const uint32_t a[4],
                                         const uint32_t b[2]) {
    asm volatile(
        "mma.sync.aligned.m16n8k8.row.col.f32.tf32.tf32.f32 "
        "{%0,%1,%2,%3}, {%4,%5,%6,%7}, {%8,%9}, {%0,%1,%2,%3};"
        : "+f"(c[0]), "+f"(c[1]), "+f"(c[2]), "+f"(c[3])
        : "r"(a[0]), "r"(a[1]), "r"(a[2]), "r"(a[3]), "r"(b[0]), "r"(b[1]));
}

// ---------------------------------------------------------------------------
// tf32 GEMM: C[m,n] = sum_k A[m,k] * Bw[n,k]  (K = 1024).
// Tile 128x128, BK=16, double-buffered. 256 threads, 8 warps as 2(m) x 4(n),
// each warp 64x32 = 4 mtiles x 4 ntiles of m16n8k8.
// MODE 0: A = x, scatter into g_q/g_k/g_v.  MODE 1: A = g_o, store to C.
// ---------------------------------------------------------------------------
#define ASTR 20   // smem row stride (floats): conflict-free fragment loads

template <int MODE>
__global__ void __launch_bounds__(256) gemm_tf32(const float* __restrict__ A,
                                                 const float* __restrict__ Bw,
                                                 float* __restrict__ C)
{
    __shared__ uint32_t As[2][128 * ASTR];
    __shared__ uint32_t Bs[2][128 * ASTR];

    const int tid = threadIdx.x;
    const int bm = blockIdx.y * 128;
    const int bn = blockIdx.x * 128;
    const float* Ap = (MODE == 1) ? (const float*)g_o : A;

    const int lane = tid & 31;
    const int warp = tid >> 5;
    const int wm = (warp >> 2) * 64;   // warp m offset (0,64)
    const int wn = (warp & 3) * 32;    // warp n offset
    const int g = lane >> 2;           // groupID
    const int t = lane & 3;            // threadID_in_group

    // global load mapping: 512 float4 per tile, 2 per thread
    int f4a = tid, f4b = tid + 256;
    const int ar0 = f4a >> 2, aq0 = (f4a & 3) * 4;
    const int ar1 = f4b >> 2, aq1 = (f4b & 3) * 4;

    const float* aBase = Ap + (size_t)bm * 1024;
    const float* bBase = Bw + (size_t)bn * 1024;

    float c[4][4][4];
#pragma unroll
    for (int i = 0; i < 4; i++)
#pragma unroll
        for (int j = 0; j < 4; j++)
#pragma unroll
            for (int e = 0; e < 4; e++) c[i][j][e] = 0.f;

    // prologue: stage 0
    {
        float4 a0 = *(const float4*)(aBase + (size_t)ar0 * 1024 + aq0);
        float4 a1 = *(const float4*)(aBase + (size_t)ar1 * 1024 + aq1);
        float4 b0 = *(const float4*)(bBase + (size_t)ar0 * 1024 + aq0);
        float4 b1 = *(const float4*)(bBase + (size_t)ar1 * 1024 + aq1);
        As[0][ar0 * ASTR + aq0 + 0] = f2tf32(a0.x);
        As[0][ar0 * ASTR + aq0 + 1] = f2tf32(a0.y);
        As[0][ar0 * ASTR + aq0 + 2] = f2tf32(a0.z);
        As[0][ar0 * ASTR + aq0 + 3] = f2tf32(a0.w);
        As[0][ar1 * ASTR + aq1 + 0] = f2tf32(a1.x);
        As[0][ar1 * ASTR + aq1 + 1] = f2tf32(a1.y);
        As[0][ar1 * ASTR + aq1 + 2] = f2tf32(a1.z);
        As[0][ar1 * ASTR + aq1 + 3] = f2tf32(a1.w);
        Bs[0][ar0 * ASTR + aq0 + 0] = f2tf32(b0.x);
        Bs[0][ar0 * ASTR + aq0 + 1] = f2tf32(b0.y);
        Bs[0][ar0 * ASTR + aq0 + 2] = f2tf32(b0.z);
        Bs[0][ar0 * ASTR + aq0 + 3] = f2tf32(b0.w);
        Bs[0][ar1 * ASTR + aq1 + 0] = f2tf32(b1.x);
        Bs[0][ar1 * ASTR + aq1 + 1] = f2tf32(b1.y);
        Bs[0][ar1 * ASTR + aq1 + 2] = f2tf32(b1.z);
        Bs[0][ar1 * ASTR + aq1 + 3] = f2tf32(b1.w);
    }
    __syncthreads();

    for (int s = 0; s < 64; s++) {
        const int buf = s & 1;
        float4 pa0, pa1, pb0, pb1;
        if (s < 63) {
            int kt = (s + 1) * 16;
            pa0 = *(const float4*)(aBase + (size_t)ar0 * 1024 + kt + aq0);
            pa1 = *(const float4*)(aBase + (size_t)ar1 * 1024 + kt + aq1);
            pb0 = *(const float4*)(bBase + (size_t)ar0 * 1024 + kt + aq0);
            pb1 = *(const float4*)(bBase + (size_t)ar1 * 1024 + kt + aq1);
        }

#pragma unroll
        for (int k0 = 0; k0 < 16; k0 += 8) {
            uint32_t af[4][4];
#pragma unroll
            for (int mt = 0; mt < 4; mt++) {
                int m0 = wm + mt * 16;
                af[mt][0] = As[buf][(m0 + g) * ASTR + k0 + t];
                af[mt][1] = As[buf][(m0 + g + 8) * ASTR + k0 + t];
                af[mt][2] = As[buf][(m0 + g) * ASTR + k0 + t + 4];
                af[mt][3] = As[buf][(m0 + g + 8) * ASTR + k0 + t + 4];
            }
#pragma unroll
            for (int nt = 0; nt < 4; nt++) {
                int n0 = wn + nt * 8;
                uint32_t bf[2];
                bf[0] = Bs[buf][(n0 + g) * ASTR + k0 + t];
                bf[1] = Bs[buf][(n0 + g) * ASTR + k0 + t + 4];
#pragma unroll
                for (int mt = 0; mt < 4; mt++) mma_tf32(c[mt][nt], af[mt], bf);
            }
        }

        if (s < 63) {
            const int nb = buf ^ 1;
            As[nb][ar0 * ASTR + aq0 + 0] = f2tf32(pa0.x);
            As[nb][ar0 * ASTR + aq0 + 1] = f2tf32(pa0.y);
            As[nb][ar0 * ASTR + aq0 + 2] = f2tf32(pa0.z);
            As[nb][ar0 * ASTR + aq0 + 3] = f2tf32(pa0.w);
            As[nb][ar1 * ASTR + aq1 + 0] = f2tf32(pa1.x);
            As[nb][ar1 * ASTR + aq1 + 1] = f2tf32(pa1.y);
            As[nb][ar1 * ASTR + aq1 + 2] = f2tf32(pa1.z);
            As[nb][ar1 * ASTR + aq1 + 3] = f2tf32(pa1.w);
            Bs[nb][ar0 * ASTR + aq0 + 0] = f2tf32(pb0.x);
            Bs[nb][ar0 * ASTR + aq0 + 1] = f2tf32(pb0.y);
            Bs[nb][ar0 * ASTR + aq0 + 2] = f2tf32(pb0.z);
            Bs[nb][ar0 * ASTR + aq0 + 3] = f2tf32(pb0.w);
            Bs[nb][ar1 * ASTR + aq1 + 0] = f2tf32(pb1.x);
            Bs[nb][ar1 * ASTR + aq1 + 1] = f2tf32(pb1.y);
            Bs[nb][ar1 * ASTR + aq1 + 2] = f2tf32(pb1.z);
            Bs[nb][ar1 * ASTR + aq1 + 3] = f2tf32(pb1.w);
        }
        __syncthreads();
    }

    if (MODE == 0) {
#pragma unroll
        for (int mt = 0; mt < 4; mt++) {
#pragma unroll
            for (int nt = 0; nt < 4; nt++) {
#pragma unroll
                for (int e = 0; e < 4; e++) {
                    int m = bm + wm + mt * 16 + g + ((e >= 2) ? 8 : 0);
                    int n = bn + wn + nt * 8 + 2 * t + (e & 1);
                    int b_ = m >> 11, s_ = m & 2047;
                    int which = n >> 10, r = n & 1023;
                    int h = r >> 6, d = r & 63;
                    float* dst = (which == 0) ? g_q : (which == 1) ? g_k : g_v;
                    dst[(((size_t)b_ * NH + h) * S_LEN + s_) * HD + d] = c[mt][nt][e];
                }
            }
        }
    } else {
#pragma unroll
        for (int mt = 0; mt < 4; mt++) {
#pragma unroll
            for (int nt = 0; nt < 4; nt++) {
                size_t r0 = (size_t)(bm + wm + mt * 16 + g) * 1024 + bn + wn + nt * 8 + 2 * t;
                size_t r1 = r0 + 8 * 1024;
                *(float2*)&C[r0] = make_float2(c[mt][nt][0], c[mt][nt][1]);
                *(float2*)&C[r1] = make_float2(c[mt][nt][2], c[mt][nt][3]);
            }
        }
    }
}

// ---------------------------------------------------------------------------
// Flash attention, tf32 mma. Block = 64 query rows of one (b,h); 128 threads,
// 4 warps x 16 rows. Q frags in registers; K smem reused as P; V smem.
// ---------------------------------------------------------------------------
#define KSTR 68   // K/P smem stride: conflict-free for B(S) and A(PV) frags
#define VSTR 72   // V smem stride: conflict-free for B(PV) frags

__global__ void __launch_bounds__(128) flash_tf32()
{
    __shared__ uint32_t KP[64 * KSTR];
    __shared__ uint32_t Vsm[64 * VSTR];

    const int tid = threadIdx.x;
    const int lane = tid & 31;
    const int warp = tid >> 5;
    const int g = lane >> 2;
    const int t = lane & 3;
    const int w16 = warp * 16;

    const int qt = blockIdx.x;   // query tile (64 rows)
    const int bh = blockIdx.y;   // b*16+h

    const float* qg = g_q + (size_t)bh * S_LEN * HD;
    const float* kg = g_k + (size_t)bh * S_LEN * HD;
    const float* vg = g_v + (size_t)bh * S_LEN * HD;

    // Q fragments (scale folded in), 8 k-steps of d
    uint32_t qf[8][4];
    {
        const float* qb = qg + (size_t)(qt * 64 + w16) * HD;
#pragma unroll
        for (int ks = 0; ks < 8; ks++) {
            int col = ks * 8;
            qf[ks][0] = f2tf32(ATT_SCALE * qb[(g)     * HD + col + t]);
            qf[ks][1] = f2tf32(ATT_SCALE * qb[(g + 8) * HD + col + t]);
            qf[ks][2] = f2tf32(ATT_SCALE * qb[(g)     * HD + col + t + 4]);
            qf[ks][3] = f2tf32(ATT_SCALE * qb[(g + 8) * HD + col + t + 4]);
        }
    }

    float m0 = -1e30f, m1 = -1e30f, l0 = 0.f, l1 = 0.f;
    float o[8][4];
#pragma unroll
    for (int nt = 0; nt < 8; nt++)
#pragma unroll
        for (int e = 0; e < 4; e++) o[nt][e] = 0.f;

    for (int kt = 0; kt < 32; kt++) {
        __syncthreads();   // previous-iteration P/V reads complete
        // load K and V tiles (64x64): 8 float4 each per thread
        {
            const float* kb = kg + (size_t)kt * 64 * HD;
            const float* vb = vg + (size_t)kt * 64 * HD;
#pragma unroll
            for (int i = 0; i < 8; i++) {
                int f4 = tid + 128 * i;
                int row = f4 >> 4;
                int cq = (f4 & 15) * 4;
                float4 kv = *(const float4*)(kb + (size_t)row * HD + cq);
                float4 vv = *(const float4*)(vb + (size_t)row * HD + cq);
                KP[row * KSTR + cq + 0] = f2tf32(kv.x);
                KP[row * KSTR + cq + 1] = f2tf32(kv.y);
                KP[row * KSTR + cq + 2] = f2tf32(kv.z);
                KP[row * KSTR + cq + 3] = f2tf32(kv.w);
                Vsm[row * VSTR + cq + 0] = f2tf32(vv.x);
                Vsm[row * VSTR + cq + 1] = f2tf32(vv.y);
                Vsm[row * VSTR + cq + 2] = f2tf32(vv.z);
                Vsm[row * VSTR + cq + 3] = f2tf32(vv.w);
            }
        }
        __syncthreads();

        // S = Q @ K^T  (16 rows x 64 keys per warp)
        float sc[8][4];
#pragma unroll
        for (int nt = 0; nt < 8; nt++) {
#pragma unroll
            for (int e = 0; e < 4; e++) sc[nt][e] = 0.f;
#pragma unroll
            for (int ks = 0; ks < 8; ks++) {
                uint32_t bf[2];
                bf[0] = KP[(nt * 8 + g) * KSTR + ks * 8 + t];
                bf[1] = KP[(nt * 8 + g) * KSTR + ks * 8 + t + 4];
                mma_tf32(sc[nt], qf[ks], bf);
            }
        }

        // online softmax (rows g and g+8; group = 4 consecutive lanes)
        float rm0 = -1e30f, rm1 = -1e30f;
#pragma unroll
        for (int nt = 0; nt < 8; nt++) {
            rm0 = fmaxf(rm0, fmaxf(sc[nt][0], sc[nt][1]));
            rm1 = fmaxf(rm1, fmaxf(sc[nt][2], sc[nt][3]));
        }
        rm0 = fmaxf(rm0, __shfl_xor_sync(0xffffffffu, rm0, 1));
        rm0 = fmaxf(rm0, __shfl_xor_sync(0xffffffffu, rm0, 2));
        rm1 = fmaxf(rm1, __shfl_xor_sync(0xffffffffu, rm1, 1));
        rm1 = fmaxf(rm1, __shfl_xor_sync(0xffffffffu, rm1, 2));
        float mn0 = fmaxf(m0, rm0), mn1 = fmaxf(m1, rm1);
        float sc0 = __expf(m0 - mn0), sc1 = __expf(m1 - mn1);
        float rs0 = 0.f, rs1 = 0.f;
#pragma unroll
        for (int nt = 0; nt < 8; nt++) {
            sc[nt][0] = __expf(sc[nt][0] - mn0);
            sc[nt][1] = __expf(sc[nt][1] - mn0);
            sc[nt][2] = __expf(sc[nt][2] - mn1);
            sc[nt][3] = __expf(sc[nt][3] - mn1);
            rs0 += sc[nt][0] + sc[nt][1];
            rs1 += sc[nt][2] + sc[nt][3];
        }
        rs0 += __shfl_xor_sync(0xffffffffu, rs0, 1);
        rs0 += __shfl_xor_sync(0xffffffffu, rs0, 2);
        rs1 += __shfl_xor_sync(0xffffffffu, rs1, 1);
        rs1 += __shfl_xor_sync(0xffffffffu, rs1, 2);
        l0 = l0 * sc0 + rs0;
        l1 = l1 * sc1 + rs1;
        m0 = mn0; m1 = mn1;
#pragma unroll
        for (int nt = 0; nt < 8; nt++) {
            o[nt][0] *= sc0; o[nt][1] *= sc0;
            o[nt][2] *= sc1; o[nt][3] *= sc1;
        }

        __syncthreads();   // all warps done reading K tile -> reuse as P
#pragma unroll
        for (int nt = 0; nt < 8; nt++) {
            int col = nt * 8 + 2 * t;
            KP[(w16 + g) * KSTR + col]     = f2tf32(sc[nt][0]);
            KP[(w16 + g) * KSTR + col + 1] = f2tf32(sc[nt][1]);
            KP[(w16 + g + 8) * KSTR + col]     = f2tf32(sc[nt][2]);
            KP[(w16 + g + 8) * KSTR + col + 1] = f2tf32(sc[nt][3]);
        }
        __syncwarp();

        // O += P @ V  (warp reads only its own 16 P rows)
#pragma unroll
        for (int ks = 0; ks < 8; ks++) {
            uint32_t af[4];
            af[0] = KP[(w16 + g) * KSTR + ks * 8 + t];
            af[1] = KP[(w16 + g + 8) * KSTR + ks * 8 + t];
            af[2] = KP[(w16 + g) * KSTR + ks * 8 + t + 4];
            af[3] = KP[(w16 + g + 8) * KSTR + ks * 8 + t + 4];
#pragma unroll
            for (int nt = 0; nt < 8; nt++) {
                uint32_t bf[2];
                bf[0] = Vsm[(ks * 8 + t) * VSTR + nt * 8 + g];
                bf[1] = Vsm[(ks * 8 + t + 4) * VSTR + nt * 8 + g];
                mma_tf32(o[nt], af, bf);
            }
        }
    }

    // normalize + write to g_o [b][s][h*64+d]
    const int b_ = bh >> 4;
    const int h = bh & 15;
    float i0 = 1.f / l0, i1 = 1.f / l1;
    size_t row0 = ((size_t)b_ * S_LEN + qt * 64 + w16 + g) * 1024 + h * HD;
    size_t row1 = row0 + 8 * 1024;
#pragma unroll
    for (int nt = 0; nt < 8; nt++) {
        int col = nt * 8 + 2 * t;
        *(float2*)&g_o[row0 + col] = make_float2(o[nt][0] * i0, o[nt][1] * i0);
        *(float2*)&g_o[row1 + col] = make_float2(o[nt][2] * i1, o[nt][3] * i1);
    }
}

// ---------------------------------------------------------------------------
extern "C" void kernel_launch(void* const* d_in, const int* in_sizes, int n_in,
                              void* d_out, int out_size)
{
    const float* x     = (const float*)d_in[0];   // [2,2048,1024]
    const float* qkv_w = (const float*)d_in[1];   // [3072,1024]
    const float* out_w = (const float*)d_in[2];   // [1024,1024]
    float* out = (float*)d_out;                   // [2,2048,1024]

    gemm_tf32<0><<<dim3(24, 32), 256>>>(x, qkv_w, nullptr);
    flash_tf32<<<dim3(32, 32), 128>>>();
    gemm_tf32<1><<<dim3(8, 32), 256>>>(nullptr, out_w, out);
}

// round 4
// speedup vs baseline: 6.1256x; 1.8711x over previous
#include <cuda_runtime.h>
#include <cuda_fp16.h>
#include <cstdint>

#define S_LEN 2048
#define NH 16
#define HD 64
#define NB 2
#define ATT_SCALE 0.125f

// fp16 scratch (allocation-free rule: __device__ globals)
__device__ __half g_q[NB * NH * S_LEN * HD];   // [b][h][s][d], pre-scaled by ATT_SCALE
__device__ __half g_k[NB * NH * S_LEN * HD];
__device__ __half g_v[NB * NH * S_LEN * HD];
__device__ __half g_o[NB * S_LEN * 1024];      // [b][s][h*64+d]

__device__ __forceinline__ uint32_t pack_h2(float x, float y) {
    __half2 h = __floats2half2_rn(x, y);
    return *reinterpret_cast<uint32_t*>(&h);
}

__device__ __forceinline__ void mma_f16(float c[4], const uint32_t a[4],
                                        uint32_t b0, uint32_t b1) {
    asm volatile(
        "mma.sync.aligned.m16n8k16.row.col.f32.f16.f16.f32 "
        "{%0,%1,%2,%3}, {%4,%5,%6,%7}, {%8,%9}, {%0,%1,%2,%3};"
        : "+f"(c[0]), "+f"(c[1]), "+f"(c[2]), "+f"(c[3])
        : "r"(a[0]), "r"(a[1]), "r"(a[2]), "r"(a[3]), "r"(b0), "r"(b1));
}

__device__ __forceinline__ void ldsm_x4(uint32_t r[4], uint32_t addr) {
    asm volatile("ldmatrix.sync.aligned.m8n8.x4.shared.b16 {%0,%1,%2,%3}, [%4];"
                 : "=r"(r[0]), "=r"(r[1]), "=r"(r[2]), "=r"(r[3]) : "r"(addr));
}
__device__ __forceinline__ void ldsm_x4t(uint32_t r[4], uint32_t addr) {
    asm volatile("ldmatrix.sync.aligned.m8n8.x4.trans.shared.b16 {%0,%1,%2,%3}, [%4];"
                 : "=r"(r[0]), "=r"(r[1]), "=r"(r[2]), "=r"(r[3]) : "r"(addr));
}

// ---------------------------------------------------------------------------
// fp16 GEMM: C[m,n] = sum_k A[m,k] * Bw[n,k]  (K = 1024), fp32 accumulate.
// Tile 128x128, BK=16, double-buffered. 256 thr, 8 warps 2(m)x4(n), 64x32/warp.
// MODE 0: A = x (f32), scatter f16 into g_q(scaled)/g_k/g_v.
// MODE 1: A = g_o (f16), store f32 C.
// ---------------------------------------------------------------------------
#define GH 24   // halves per smem row (48B): 48*i mod 128 spans all 16B phases

template <int MODE>
__global__ void __launch_bounds__(256) gemm_f16(const float* __restrict__ A,
                                                const float* __restrict__ Bw,
                                                float* __restrict__ C)
{
    __shared__ __half As[2][128 * GH];
    __shared__ __half Bs[2][128 * GH];

    const int tid = threadIdx.x, lane = tid & 31, warp = tid >> 5;
    const int bm = blockIdx.y * 128, bn = blockIdx.x * 128;
    const int wm = (warp >> 2) * 64, wn = (warp & 3) * 32;
    const int g = lane >> 2, t = lane & 3;

    const float* bBase = Bw + (size_t)bn * 1024;
    const float* aBaseF = A + (size_t)bm * 1024;
    const __half* aBaseH = g_o + (size_t)bm * 1024;

    const uint32_t asb = (uint32_t)__cvta_generic_to_shared(&As[0][0]);
    const uint32_t bsb = (uint32_t)__cvta_generic_to_shared(&Bs[0][0]);
    const uint32_t bufstride = 128 * GH * 2;

    uint32_t offa[4], offb[2];
#pragma unroll
    for (int mt = 0; mt < 4; mt++)
        offa[mt] = ((wm + mt * 16 + (lane & 15)) * GH + (lane >> 4) * 8) * 2;
#pragma unroll
    for (int np = 0; np < 2; np++)
        offb[np] = ((wn + np * 16 + (lane & 7) + ((lane >> 4) & 1) * 8) * GH + (lane & 8)) * 2;

    // global load mapping
    const int br0 = tid >> 2,          bc0 = (tid & 3) * 4;          // f32 float4 slot (tid)
    const int br1 = (tid + 256) >> 2,  bc1 = ((tid + 256) & 3) * 4;  // f32 float4 slot (tid+256)
    const int hrow = tid >> 1,         hch = (tid & 1) * 8;          // MODE1 A f16 16B chunk

    float c[4][4][4];
#pragma unroll
    for (int i = 0; i < 4; i++)
#pragma unroll
        for (int j = 0; j < 4; j++)
#pragma unroll
            for (int e = 0; e < 4; e++) c[i][j][e] = 0.f;

    // --- stage 0 load ---
    {
        float4 b0 = *(const float4*)(bBase + (size_t)br0 * 1024 + bc0);
        float4 b1 = *(const float4*)(bBase + (size_t)br1 * 1024 + bc1);
        *(__half2*)&Bs[0][br0 * GH + bc0]     = __floats2half2_rn(b0.x, b0.y);
        *(__half2*)&Bs[0][br0 * GH + bc0 + 2] = __floats2half2_rn(b0.z, b0.w);
        *(__half2*)&Bs[0][br1 * GH + bc1]     = __floats2half2_rn(b1.x, b1.y);
        *(__half2*)&Bs[0][br1 * GH + bc1 + 2] = __floats2half2_rn(b1.z, b1.w);
        if (MODE == 0) {
            float4 a0 = *(const float4*)(aBaseF + (size_t)br0 * 1024 + bc0);
            float4 a1 = *(const float4*)(aBaseF + (size_t)br1 * 1024 + bc1);
            *(__half2*)&As[0][br0 * GH + bc0]     = __floats2half2_rn(a0.x, a0.y);
            *(__half2*)&As[0][br0 * GH + bc0 + 2] = __floats2half2_rn(a0.z, a0.w);
            *(__half2*)&As[0][br1 * GH + bc1]     = __floats2half2_rn(a1.x, a1.y);
            *(__half2*)&As[0][br1 * GH + bc1 + 2] = __floats2half2_rn(a1.z, a1.w);
        } else {
            *(float4*)&As[0][hrow * GH + hch] =
                *(const float4*)(aBaseH + (size_t)hrow * 1024 + hch);
        }
    }
    __syncthreads();

    for (int s = 0; s < 64; s++) {
        const int buf = s & 1;
        float4 pb0, pb1, pa0, pa1, pah;
        if (s < 63) {
            const int kt = (s + 1) * 16;
            pb0 = *(const float4*)(bBase + (size_t)br0 * 1024 + kt + bc0);
            pb1 = *(const float4*)(bBase + (size_t)br1 * 1024 + kt + bc1);
            if (MODE == 0) {
                pa0 = *(const float4*)(aBaseF + (size_t)br0 * 1024 + kt + bc0);
                pa1 = *(const float4*)(aBaseF + (size_t)br1 * 1024 + kt + bc1);
            } else {
                pah = *(const float4*)(aBaseH + (size_t)hrow * 1024 + kt + hch);
            }
        }

        const uint32_t ab = asb + buf * bufstride;
        const uint32_t bb = bsb + buf * bufstride;
        uint32_t af[4][4], bf[2][4];
#pragma unroll
        for (int mt = 0; mt < 4; mt++) ldsm_x4(af[mt], ab + offa[mt]);
#pragma unroll
        for (int np = 0; np < 2; np++) ldsm_x4(bf[np], bb + offb[np]);
#pragma unroll
        for (int nt = 0; nt < 4; nt++) {
            uint32_t b0 = bf[nt >> 1][(nt & 1) * 2];
            uint32_t b1 = bf[nt >> 1][(nt & 1) * 2 + 1];
#pragma unroll
            for (int mt = 0; mt < 4; mt++) mma_f16(c[mt][nt], af[mt], b0, b1);
        }

        if (s < 63) {
            const int nb = buf ^ 1;
            *(__half2*)&Bs[nb][br0 * GH + bc0]     = __floats2half2_rn(pb0.x, pb0.y);
            *(__half2*)&Bs[nb][br0 * GH + bc0 + 2] = __floats2half2_rn(pb0.z, pb0.w);
            *(__half2*)&Bs[nb][br1 * GH + bc1]     = __floats2half2_rn(pb1.x, pb1.y);
            *(__half2*)&Bs[nb][br1 * GH + bc1 + 2] = __floats2half2_rn(pb1.z, pb1.w);
            if (MODE == 0) {
                *(__half2*)&As[nb][br0 * GH + bc0]     = __floats2half2_rn(pa0.x, pa0.y);
                *(__half2*)&As[nb][br0 * GH + bc0 + 2] = __floats2half2_rn(pa0.z, pa0.w);
                *(__half2*)&As[nb][br1 * GH + bc1]     = __floats2half2_rn(pa1.x, pa1.y);
                *(__half2*)&As[nb][br1 * GH + bc1 + 2] = __floats2half2_rn(pa1.z, pa1.w);
            } else {
                *(float4*)&As[nb][hrow * GH + hch] = pah;
            }
        }
        __syncthreads();
    }

    if (MODE == 0) {
#pragma unroll
        for (int mt = 0; mt < 4; mt++) {
            const int m0 = bm + wm + mt * 16 + g;
            const int b0_ = m0 >> 11, s0_ = m0 & 2047;
            const int m1 = m0 + 8;
            const int b1_ = m1 >> 11, s1_ = m1 & 2047;
#pragma unroll
            for (int nt = 0; nt < 4; nt++) {
                const int n = bn + wn + nt * 8 + 2 * t;   // even
                const int which = n >> 10;
                const int r = n & 1023;
                const int h = r >> 6, d = r & 63;
                __half* dst = (which == 0) ? g_q : (which == 1) ? g_k : g_v;
                const float sc = (which == 0) ? ATT_SCALE : 1.f;
                size_t i0 = (((size_t)b0_ * NH + h) * S_LEN + s0_) * HD + d;
                size_t i1 = (((size_t)b1_ * NH + h) * S_LEN + s1_) * HD + d;
                *(__half2*)&dst[i0] = __floats2half2_rn(c[mt][nt][0] * sc, c[mt][nt][1] * sc);
                *(__half2*)&dst[i1] = __floats2half2_rn(c[mt][nt][2] * sc, c[mt][nt][3] * sc);
            }
        }
    } else {
#pragma unroll
        for (int mt = 0; mt < 4; mt++) {
#pragma unroll
            for (int nt = 0; nt < 4; nt++) {
                size_t r0 = (size_t)(bm + wm + mt * 16 + g) * 1024 + bn + wn + nt * 8 + 2 * t;
                *(float2*)&C[r0]        = make_float2(c[mt][nt][0], c[mt][nt][1]);
                *(float2*)&C[r0 + 8192] = make_float2(c[mt][nt][2], c[mt][nt][3]);
            }
        }
    }
}

// ---------------------------------------------------------------------------
// Flash attention, fp16 mma. Block = 64 q rows of one (b,h); 128 thr, 4 warps.
// Q frags in regs (pre-scaled f16); K,V tiles in smem (ldmatrix);
// P stays in registers (C-frag == A-frag layout for m16n8k16).
// ---------------------------------------------------------------------------
#define FH 72   // halves per smem row (144B). Tile is 64 cols; 8 pad halves.
                // 144 mod 128 = 16 -> 8 consecutive rows hit all 8 16B phases.

__global__ void __launch_bounds__(128) flash_f16()
{
    __shared__ __half Ks[64 * FH];
    __shared__ __half Vs[64 * FH];

    const int tid = threadIdx.x, lane = tid & 31, warp = tid >> 5;
    const int g = lane >> 2, t = lane & 3;
    const int w16 = warp * 16;
    const int qt = blockIdx.x;   // query tile (64 rows)
    const int bh = blockIdx.y;   // b*16+h

    const __half* qg = g_q + (size_t)bh * S_LEN * HD;
    const __half* kg = g_k + (size_t)bh * S_LEN * HD;
    const __half* vg = g_v + (size_t)bh * S_LEN * HD;

    // Q fragments: direct half2 loads (scale folded at projection)
    uint32_t qf[4][4];
    {
        const __half* qb = qg + (size_t)(qt * 64 + w16) * HD;
#pragma unroll
        for (int ks = 0; ks < 4; ks++) {
            const int c0 = ks * 16 + 2 * t;
            qf[ks][0] = *(const uint32_t*)&qb[(size_t)g * HD + c0];
            qf[ks][1] = *(const uint32_t*)&qb[(size_t)(g + 8) * HD + c0];
            qf[ks][2] = *(const uint32_t*)&qb[(size_t)g * HD + c0 + 8];
            qf[ks][3] = *(const uint32_t*)&qb[(size_t)(g + 8) * HD + c0 + 8];
        }
    }

    const uint32_t ksb = (uint32_t)__cvta_generic_to_shared(Ks);
    const uint32_t vsb = (uint32_t)__cvta_generic_to_shared(Vs);
    uint32_t offs[4], offv[4];
#pragma unroll
    for (int np = 0; np < 4; np++)
        offs[np] = ((np * 16 + (lane & 7) + ((lane >> 4) & 1) * 8) * FH + (lane & 8)) * 2;
#pragma unroll
    for (int dp = 0; dp < 4; dp++)
        offv[dp] = (((lane & 7) + (lane & 8)) * FH + dp * 16 + ((lane >> 4) & 1) * 8) * 2;

    float m0 = -1e30f, m1 = -1e30f, l0 = 0.f, l1 = 0.f;
    float o[8][4];
#pragma unroll
    for (int nt = 0; nt < 8; nt++)
#pragma unroll
        for (int e = 0; e < 4; e++) o[nt][e] = 0.f;

    for (int kt = 0; kt < 32; kt++) {
        __syncthreads();   // previous-iteration smem reads complete
        {
            const __half* kb = kg + (size_t)kt * 64 * HD;
            const __half* vb = vg + (size_t)kt * 64 * HD;
#pragma unroll
            for (int i = 0; i < 4; i++) {
                const int c16 = tid + 128 * i;        // 16B chunks
                const int row = c16 >> 3, ch = (c16 & 7) * 8;
                *(float4*)&Ks[row * FH + ch] = *(const float4*)&kb[(size_t)row * HD + ch];
                *(float4*)&Vs[row * FH + ch] = *(const float4*)&vb[(size_t)row * HD + ch];
            }
        }
        __syncthreads();

        // S = Q @ K^T
        float sc[8][4];
#pragma unroll
        for (int nt = 0; nt < 8; nt++)
#pragma unroll
            for (int e = 0; e < 4; e++) sc[nt][e] = 0.f;
#pragma unroll
        for (int ks = 0; ks < 4; ks++) {
#pragma unroll
            for (int np = 0; np < 4; np++) {
                uint32_t bf[4];
                ldsm_x4(bf, ksb + offs[np] + ks * 32);
                mma_f16(sc[np * 2],     qf[ks], bf[0], bf[1]);
                mma_f16(sc[np * 2 + 1], qf[ks], bf[2], bf[3]);
            }
        }

        // online softmax (scale already folded into Q)
        float rm0 = -1e30f, rm1 = -1e30f;
#pragma unroll
        for (int nt = 0; nt < 8; nt++) {
            rm0 = fmaxf(rm0, fmaxf(sc[nt][0], sc[nt][1]));
            rm1 = fmaxf(rm1, fmaxf(sc[nt][2], sc[nt][3]));
        }
        rm0 = fmaxf(rm0, __shfl_xor_sync(0xffffffffu, rm0, 1));
        rm0 = fmaxf(rm0, __shfl_xor_sync(0xffffffffu, rm0, 2));
        rm1 = fmaxf(rm1, __shfl_xor_sync(0xffffffffu, rm1, 1));
        rm1 = fmaxf(rm1, __shfl_xor_sync(0xffffffffu, rm1, 2));
        const float mn0 = fmaxf(m0, rm0), mn1 = fmaxf(m1, rm1);
        const float e0 = __expf(m0 - mn0), e1 = __expf(m1 - mn1);
        float rs0 = 0.f, rs1 = 0.f;
#pragma unroll
        for (int nt = 0; nt < 8; nt++) {
            sc[nt][0] = __expf(sc[nt][0] - mn0);
            sc[nt][1] = __expf(sc[nt][1] - mn0);
            sc[nt][2] = __expf(sc[nt][2] - mn1);
            sc[nt][3] = __expf(sc[nt][3] - mn1);
            rs0 += sc[nt][0] + sc[nt][1];
            rs1 += sc[nt][2] + sc[nt][3];
        }
        rs0 += __shfl_xor_sync(0xffffffffu, rs0, 1);
        rs0 += __shfl_xor_sync(0xffffffffu, rs0, 2);
        rs1 += __shfl_xor_sync(0xffffffffu, rs1, 1);
        rs1 += __shfl_xor_sync(0xffffffffu, rs1, 2);
        l0 = l0 * e0 + rs0;
        l1 = l1 * e1 + rs1;
        m0 = mn0; m1 = mn1;
#pragma unroll
        for (int nt = 0; nt < 8; nt++) {
            o[nt][0] *= e0; o[nt][1] *= e0;
            o[nt][2] *= e1; o[nt][3] *= e1;
        }

        // O += P @ V  (P built from S C-frags in registers)
#pragma unroll
        for (int ks = 0; ks < 4; ks++) {
            uint32_t pa[4];
            pa[0] = pack_h2(sc[2 * ks][0],     sc[2 * ks][1]);
            pa[1] = pack_h2(sc[2 * ks][2],     sc[2 * ks][3]);
            pa[2] = pack_h2(sc[2 * ks + 1][0], sc[2 * ks + 1][1]);
            pa[3] = pack_h2(sc[2 * ks + 1][2], sc[2 * ks + 1][3]);
#pragma unroll
            for (int dp = 0; dp < 4; dp++) {
                uint32_t bf[4];
                ldsm_x4t(bf, vsb + offv[dp] + ks * 16 * FH * 2);
                mma_f16(o[dp * 2],     pa, bf[0], bf[1]);
                mma_f16(o[dp * 2 + 1], pa, bf[2], bf[3]);
            }
        }
    }

    // normalize + write f16 to g_o [b][s][h*64+d]
    const int b_ = bh >> 4;
    const int h = bh & 15;
    const float i0 = 1.f / l0, i1 = 1.f / l1;
    size_t row0 = ((size_t)b_ * S_LEN + qt * 64 + w16 + g) * 1024 + h * HD;
    size_t row1 = row0 + 8 * 1024;
#pragma unroll
    for (int nt = 0; nt < 8; nt++) {
        const int col = nt * 8 + 2 * t;
        *(__half2*)&g_o[row0 + col] = __floats2half2_rn(o[nt][0] * i0, o[nt][1] * i0);
        *(__half2*)&g_o[row1 + col] = __floats2half2_rn(o[nt][2] * i1, o[nt][3] * i1);
    }
}

// ---------------------------------------------------------------------------
extern "C" void kernel_launch(void* const* d_in, const int* in_sizes, int n_in,
                              void* d_out, int out_size)
{
    const float* x     = (const float*)d_in[0];   // [2,2048,1024]
    const float* qkv_w = (const float*)d_in[1];   // [3072,1024]
    const float* out_w = (const float*)d_in[2];   // [1024,1024]
    float* out = (float*)d_out;                   // [2,2048,1024]

    gemm_f16<0><<<dim3(24, 32), 256>>>(x, qkv_w, nullptr);
    flash_f16<<<dim3(32, 32), 128>>>();
    gemm_f16<1><<<dim3(8, 32), 256>>>(nullptr, out_w, out);
}

// round 5
// speedup vs baseline: 7.6020x; 1.2410x over previous
#include <cuda_runtime.h>
#include <cuda_fp16.h>
#include <cstdint>

#define S_LEN 2048
#define NH 16
#define HD 64
#define NB 2
#define ATT_SCALE 0.125f

// fp16 scratch (allocation-free rule: __device__ globals)
__device__ __half g_q[NB * NH * S_LEN * HD];   // [b][h][s][d], pre-scaled by ATT_SCALE
__device__ __half g_k[NB * NH * S_LEN * HD];
__device__ __half g_v[NB * NH * S_LEN * HD];
__device__ __half g_o[NB * S_LEN * 1024];      // [b][s][h*64+d]
__device__ __half g_xh[NB * S_LEN * 1024];     // x in f16
__device__ __half g_wqkv[3072 * 1024];         // qkv_w in f16
__device__ __half g_wout[1024 * 1024];         // out_w in f16

__device__ __forceinline__ uint32_t pack_h2(float x, float y) {
    __half2 h = __floats2half2_rn(x, y);
    return *reinterpret_cast<uint32_t*>(&h);
}

__device__ __forceinline__ void mma_f16(float c[4], const uint32_t a[4],
                                        uint32_t b0, uint32_t b1) {
    asm volatile(
        "mma.sync.aligned.m16n8k16.row.col.f32.f16.f16.f32 "
        "{%0,%1,%2,%3}, {%4,%5,%6,%7}, {%8,%9}, {%0,%1,%2,%3};"
        : "+f"(c[0]), "+f"(c[1]), "+f"(c[2]), "+f"(c[3])
        : "r"(a[0]), "r"(a[1]), "r"(a[2]), "r"(a[3]), "r"(b0), "r"(b1));
}

__device__ __forceinline__ void ldsm_x4(uint32_t r[4], uint32_t addr) {
    asm volatile("ldmatrix.sync.aligned.m8n8.x4.shared.b16 {%0,%1,%2,%3}, [%4];"
                 : "=r"(r[0]), "=r"(r[1]), "=r"(r[2]), "=r"(r[3]) : "r"(addr));
}
__device__ __forceinline__ void ldsm_x4t(uint32_t r[4], uint32_t addr) {
    asm volatile("ldmatrix.sync.aligned.m8n8.x4.trans.shared.b16 {%0,%1,%2,%3}, [%4];"
                 : "=r"(r[0]), "=r"(r[1]), "=r"(r[2]), "=r"(r[3]) : "r"(addr));
}

#define CP_ASYNC16(dst, src) \
    asm volatile("cp.async.cg.shared.global [%0], [%1], 16;" :: "r"(dst), "l"(src))
#define CP_COMMIT() asm volatile("cp.async.commit_group;")
#define CP_WAIT(n)  asm volatile("cp.async.wait_group %0;" :: "n"(n))

// ---------------------------------------------------------------------------
// One-shot f32 -> f16 conversion of x, qkv_w, out_w (grid-stride by float4).
// ---------------------------------------------------------------------------
#define N4_X  (NB * S_LEN * 1024 / 4)   // 1048576
#define N4_W  (3072 * 1024 / 4)         //  786432
#define N4_O  (1024 * 1024 / 4)         //  262144

__global__ void __launch_bounds__(256) convert_f16(const float* __restrict__ x,
                                                   const float* __restrict__ qkv_w,
                                                   const float* __restrict__ out_w)
{
    const int i = blockIdx.x * 256 + threadIdx.x;
    const float4* src;
    __half* dst;
    int off;
    if (i < N4_X)            { src = (const float4*)x;     dst = g_xh;   off = i; }
    else if (i < N4_X + N4_W){ src = (const float4*)qkv_w; dst = g_wqkv; off = i - N4_X; }
    else                     { src = (const float4*)out_w; dst = g_wout; off = i - N4_X - N4_W; }
    float4 v = src[off];
    *(__half2*)&dst[off * 4]     = __floats2half2_rn(v.x, v.y);
    *(__half2*)&dst[off * 4 + 2] = __floats2half2_rn(v.z, v.w);
}

// ---------------------------------------------------------------------------
// fp16 GEMM, cp.async 3-stage: C[m,n] = sum_k A[m,k]*Bw[n,k], K=1024, f32 acc.
// Tile 128x128, BK=16. 256 thr, 8 warps 2(m)x4(n), 64x32/warp.
// MODE 0: A=g_xh, scatter f16 into g_q(scaled)/g_k/g_v. MODE 1: A=g_o, f32 C.
// ---------------------------------------------------------------------------
#define GH 24            // halves/row (48B): 48*i mod 128 spans all 16B phases
#define GSTAGE (128 * GH * 2)   // bytes per stage per operand

template <int MODE>
__global__ void __launch_bounds__(256, 2) gemm_f16(const __half* __restrict__ Bw,
                                                   float* __restrict__ C)
{
    __shared__ __half As[3][128 * GH];
    __shared__ __half Bs[3][128 * GH];

    const int tid = threadIdx.x, lane = tid & 31, warp = tid >> 5;
    const int bm = blockIdx.y * 128, bn = blockIdx.x * 128;
    const int wm = (warp >> 2) * 64, wn = (warp & 3) * 32;
    const int g = lane >> 2, t = lane & 3;

    const __half* aBase = ((MODE == 0) ? g_xh : g_o) + (size_t)bm * 1024;
    const __half* bBase = Bw + (size_t)bn * 1024;

    const uint32_t asb = (uint32_t)__cvta_generic_to_shared(&As[0][0]);
    const uint32_t bsb = (uint32_t)__cvta_generic_to_shared(&Bs[0][0]);

    uint32_t offa[4], offb[2];
#pragma unroll
    for (int mt = 0; mt < 4; mt++)
        offa[mt] = ((wm + mt * 16 + (lane & 15)) * GH + (lane >> 4) * 8) * 2;
#pragma unroll
    for (int np = 0; np < 2; np++)
        offb[np] = ((wn + np * 16 + (lane & 7) + ((lane >> 4) & 1) * 8) * GH + (lane & 8)) * 2;

    // cp.async mapping: 256 chunks of 16B per operand per stage, 1 each/thread
    const int crow = tid >> 1, ccol = (tid & 1) * 8;
    const uint32_t sdst = (crow * GH + ccol) * 2;
    const __half* asrc = aBase + (size_t)crow * 1024 + ccol;
    const __half* bsrc = bBase + (size_t)crow * 1024 + ccol;

    float c[4][4][4];
#pragma unroll
    for (int i = 0; i < 4; i++)
#pragma unroll
        for (int j = 0; j < 4; j++)
#pragma unroll
            for (int e = 0; e < 4; e++) c[i][j][e] = 0.f;

    // prologue: stages 0,1
#pragma unroll
    for (int p = 0; p < 2; p++) {
        CP_ASYNC16(asb + p * GSTAGE + sdst, asrc + p * 16);
        CP_ASYNC16(bsb + p * GSTAGE + sdst, bsrc + p * 16);
        CP_COMMIT();
    }

    int buf = 0;
    for (int s = 0; s < 64; s++) {
        CP_WAIT(1);
        __syncthreads();

        if (s + 2 < 64) {
            const int nb = (buf + 2 >= 3) ? buf - 1 : buf + 2;
            CP_ASYNC16(asb + nb * GSTAGE + sdst, asrc + (s + 2) * 16);
            CP_ASYNC16(bsb + nb * GSTAGE + sdst, bsrc + (s + 2) * 16);
            CP_COMMIT();
        }

        const uint32_t ab = asb + buf * GSTAGE;
        const uint32_t bb = bsb + buf * GSTAGE;
        uint32_t af[4][4], bf[2][4];
#pragma unroll
        for (int mt = 0; mt < 4; mt++) ldsm_x4(af[mt], ab + offa[mt]);
#pragma unroll
        for (int np = 0; np < 2; np++) ldsm_x4(bf[np], bb + offb[np]);
#pragma unroll
        for (int nt = 0; nt < 4; nt++) {
            uint32_t b0 = bf[nt >> 1][(nt & 1) * 2];
            uint32_t b1 = bf[nt >> 1][(nt & 1) * 2 + 1];
#pragma unroll
            for (int mt = 0; mt < 4; mt++) mma_f16(c[mt][nt], af[mt], b0, b1);
        }
        buf = (buf == 2) ? 0 : buf + 1;
    }

    if (MODE == 0) {
#pragma unroll
        for (int mt = 0; mt < 4; mt++) {
            const int m0 = bm + wm + mt * 16 + g;
            const int b0_ = m0 >> 11, s0_ = m0 & 2047;
            const int m1 = m0 + 8;
            const int b1_ = m1 >> 11, s1_ = m1 & 2047;
#pragma unroll
            for (int nt = 0; nt < 4; nt++) {
                const int n = bn + wn + nt * 8 + 2 * t;   // even
                const int which = n >> 10;
                const int r = n & 1023;
                const int h = r >> 6, d = r & 63;
                __half* dst = (which == 0) ? g_q : (which == 1) ? g_k : g_v;
                const float sc = (which == 0) ? ATT_SCALE : 1.f;
                size_t i0 = (((size_t)b0_ * NH + h) * S_LEN + s0_) * HD + d;
                size_t i1 = (((size_t)b1_ * NH + h) * S_LEN + s1_) * HD + d;
                *(__half2*)&dst[i0] = __floats2half2_rn(c[mt][nt][0] * sc, c[mt][nt][1] * sc);
                *(__half2*)&dst[i1] = __floats2half2_rn(c[mt][nt][2] * sc, c[mt][nt][3] * sc);
            }
        }
    } else {
#pragma unroll
        for (int mt = 0; mt < 4; mt++) {
#pragma unroll
            for (int nt = 0; nt < 4; nt++) {
                size_t r0 = (size_t)(bm + wm + mt * 16 + g) * 1024 + bn + wn + nt * 8 + 2 * t;
                *(float2*)&C[r0]        = make_float2(c[mt][nt][0], c[mt][nt][1]);
                *(float2*)&C[r0 + 8192] = make_float2(c[mt][nt][2], c[mt][nt][3]);
            }
        }
    }
}

// ---------------------------------------------------------------------------
// Flash attention, fp16 mma, cp.async double-buffered K/V.
// Block = 64 q rows of one (b,h); 128 thr, 4 warps. P stays in registers.
// ---------------------------------------------------------------------------
#define FH 72                    // halves/row (144B): conflict-free ldmatrix
#define FSTAGE (64 * FH * 2)     // bytes per stage per tile

__global__ void __launch_bounds__(128) flash_f16()
{
    __shared__ __half Ks[2][64 * FH];
    __shared__ __half Vs[2][64 * FH];

    const int tid = threadIdx.x, lane = tid & 31, warp = tid >> 5;
    const int g = lane >> 2, t = lane & 3;
    const int w16 = warp * 16;
    const int qt = blockIdx.x;   // query tile (64 rows)
    const int bh = blockIdx.y;   // b*16+h

    const __half* qg = g_q + (size_t)bh * S_LEN * HD;
    const __half* kg = g_k + (size_t)bh * S_LEN * HD;
    const __half* vg = g_v + (size_t)bh * S_LEN * HD;

    // Q fragments: direct half2 loads (scale folded at projection)
    uint32_t qf[4][4];
    {
        const __half* qb = qg + (size_t)(qt * 64 + w16) * HD;
#pragma unroll
        for (int ks = 0; ks < 4; ks++) {
            const int c0 = ks * 16 + 2 * t;
            qf[ks][0] = *(const uint32_t*)&qb[(size_t)g * HD + c0];
            qf[ks][1] = *(const uint32_t*)&qb[(size_t)(g + 8) * HD + c0];
            qf[ks][2] = *(const uint32_t*)&qb[(size_t)g * HD + c0 + 8];
            qf[ks][3] = *(const uint32_t*)&qb[(size_t)(g + 8) * HD + c0 + 8];
        }
    }

    const uint32_t ksb = (uint32_t)__cvta_generic_to_shared(&Ks[0][0]);
    const uint32_t vsb = (uint32_t)__cvta_generic_to_shared(&Vs[0][0]);
    uint32_t offs[4], offv[4];
#pragma unroll
    for (int np = 0; np < 4; np++)
        offs[np] = ((np * 16 + (lane & 7) + ((lane >> 4) & 1) * 8) * FH + (lane & 8)) * 2;
#pragma unroll
    for (int dp = 0; dp < 4; dp++)
        offv[dp] = (((lane & 7) + (lane & 8)) * FH + dp * 16 + ((lane >> 4) & 1) * 8) * 2;

    // cp.async mapping: 8 chunks/thread (4 K + 4 V), 16B each
    uint32_t cdst[4];
    const __half* ksrc[4];
    const __half* vsrc0[4];
#pragma unroll
    for (int i = 0; i < 4; i++) {
        const int c16 = tid + 128 * i;
        const int row = c16 >> 3, ch = (c16 & 7) * 8;
        cdst[i] = (row * FH + ch) * 2;
        ksrc[i] = kg + (size_t)row * HD + ch;
        vsrc0[i] = vg + (size_t)row * HD + ch;
    }

    float m0 = -1e30f, m1 = -1e30f, l0 = 0.f, l1 = 0.f;
    float o[8][4];
#pragma unroll
    for (int nt = 0; nt < 8; nt++)
#pragma unroll
        for (int e = 0; e < 4; e++) o[nt][e] = 0.f;

    // prologue: stage 0
#pragma unroll
    for (int i = 0; i < 4; i++) {
        CP_ASYNC16(ksb + cdst[i], ksrc[i]);
        CP_ASYNC16(vsb + cdst[i], vsrc0[i]);
    }
    CP_COMMIT();

    for (int kt = 0; kt < 32; kt++) {
        CP_WAIT(0);
        __syncthreads();

        if (kt + 1 < 32) {
            const uint32_t nb = ((kt + 1) & 1) * FSTAGE;
            const size_t go = (size_t)(kt + 1) * 64 * HD;
#pragma unroll
            for (int i = 0; i < 4; i++) {
                CP_ASYNC16(ksb + nb + cdst[i], ksrc[i] + go);
                CP_ASYNC16(vsb + nb + cdst[i], vsrc0[i] + go);
            }
            CP_COMMIT();
        }

        const uint32_t kb = ksb + (kt & 1) * FSTAGE;
        const uint32_t vb = vsb + (kt & 1) * FSTAGE;

        // S = Q @ K^T
        float sc[8][4];
#pragma unroll
        for (int nt = 0; nt < 8; nt++)
#pragma unroll
            for (int e = 0; e < 4; e++) sc[nt][e] = 0.f;
#pragma unroll
        for (int ks = 0; ks < 4; ks++) {
#pragma unroll
            for (int np = 0; np < 4; np++) {
                uint32_t bf[4];
                ldsm_x4(bf, kb + offs[np] + ks * 32);
                mma_f16(sc[np * 2],     qf[ks], bf[0], bf[1]);
                mma_f16(sc[np * 2 + 1], qf[ks], bf[2], bf[3]);
            }
        }

        // online softmax (scale already folded into Q)
        float rm0 = -1e30f, rm1 = -1e30f;
#pragma unroll
        for (int nt = 0; nt < 8; nt++) {
            rm0 = fmaxf(rm0, fmaxf(sc[nt][0], sc[nt][1]));
            rm1 = fmaxf(rm1, fmaxf(sc[nt][2], sc[nt][3]));
        }
        rm0 = fmaxf(rm0, __shfl_xor_sync(0xffffffffu, rm0, 1));
        rm0 = fmaxf(rm0, __shfl_xor_sync(0xffffffffu, rm0, 2));
        rm1 = fmaxf(rm1, __shfl_xor_sync(0xffffffffu, rm1, 1));
        rm1 = fmaxf(rm1, __shfl_xor_sync(0xffffffffu, rm1, 2));
        const float mn0 = fmaxf(m0, rm0), mn1 = fmaxf(m1, rm1);
        const float e0 = __expf(m0 - mn0), e1 = __expf(m1 - mn1);
        float rs0 = 0.f, rs1 = 0.f;
#pragma unroll
        for (int nt = 0; nt < 8; nt++) {
            sc[nt][0] = __expf(sc[nt][0] - mn0);
            sc[nt][1] = __expf(sc[nt][1] - mn0);
            sc[nt][2] = __expf(sc[nt][2] - mn1);
            sc[nt][3] = __expf(sc[nt][3] - mn1);
            rs0 += sc[nt][0] + sc[nt][1];
            rs1 += sc[nt][2] + sc[nt][3];
        }
        rs0 += __shfl_xor_sync(0xffffffffu, rs0, 1);
        rs0 += __shfl_xor_sync(0xffffffffu, rs0, 2);
        rs1 += __shfl_xor_sync(0xffffffffu, rs1, 1);
        rs1 += __shfl_xor_sync(0xffffffffu, rs1, 2);
        l0 = l0 * e0 + rs0;
        l1 = l1 * e1 + rs1;
        m0 = mn0; m1 = mn1;
#pragma unroll
        for (int nt = 0; nt < 8; nt++) {
            o[nt][0] *= e0; o[nt][1] *= e0;
            o[nt][2] *= e1; o[nt][3] *= e1;
        }

        // O += P @ V  (P built from S C-frags in registers)
#pragma unroll
        for (int ks = 0; ks < 4; ks++) {
            uint32_t pa[4];
            pa[0] = pack_h2(sc[2 * ks][0],     sc[2 * ks][1]);
            pa[1] = pack_h2(sc[2 * ks][2],     sc[2 * ks][3]);
            pa[2] = pack_h2(sc[2 * ks + 1][0], sc[2 * ks + 1][1]);
            pa[3] = pack_h2(sc[2 * ks + 1][2], sc[2 * ks + 1][3]);
#pragma unroll
            for (int dp = 0; dp < 4; dp++) {
                uint32_t bf[4];
                ldsm_x4t(bf, vb + offv[dp] + ks * 16 * FH * 2);
                mma_f16(o[dp * 2],     pa, bf[0], bf[1]);
                mma_f16(o[dp * 2 + 1], pa, bf[2], bf[3]);
            }
        }
    }

    // normalize + write f16 to g_o [b][s][h*64+d]
    const int b_ = bh >> 4;
    const int h = bh & 15;
    const float i0 = 1.f / l0, i1 = 1.f / l1;
    size_t row0 = ((size_t)b_ * S_LEN + qt * 64 + w16 + g) * 1024 + h * HD;
    size_t row1 = row0 + 8 * 1024;
#pragma unroll
    for (int nt = 0; nt < 8; nt++) {
        const int col = nt * 8 + 2 * t;
        *(__half2*)&g_o[row0 + col] = __floats2half2_rn(o[nt][0] * i0, o[nt][1] * i0);
        *(__half2*)&g_o[row1 + col] = __floats2half2_rn(o[nt][2] * i1, o[nt][3] * i1);
    }
}

// ---------------------------------------------------------------------------
extern "C" void kernel_launch(void* const* d_in, const int* in_sizes, int n_in,
                              void* d_out, int out_size)
{
    const float* x     = (const float*)d_in[0];   // [2,2048,1024]
    const float* qkv_w = (const float*)d_in[1];   // [3072,1024]
    const float* out_w = (const float*)d_in[2];   // [1024,1024]
    float* out = (float*)d_out;                   // [2,2048,1024]

    convert_f16<<<(N4_X + N4_W + N4_O) / 256, 256>>>(x, qkv_w, out_w);

    __half* wqkv_p, * wout_p;
    cudaGetSymbolAddress((void**)&wqkv_p, g_wqkv);
    cudaGetSymbolAddress((void**)&wout_p, g_wout);

    gemm_f16<0><<<dim3(24, 32), 256>>>(wqkv_p, nullptr);
    flash_f16<<<dim3(32, 32), 128>>>();
    gemm_f16<1><<<dim3(8, 32), 256>>>(wout_p, out);
}